// round 16
// baseline (speedup 1.0000x reference)
#include <cuda_runtime.h>
#include <cuda_bf16.h>
#include <cstdint>

#define NN 4096
#define FF 512
#define DD 64
#define HH 8
#define SPLITM 2
#define SPLITO 16

// ---------------------------------------------------------------- helpers
__device__ __forceinline__ void mma_bf16(float* d, const uint32_t* a, const uint32_t* b) {
    asm volatile("mma.sync.aligned.m16n8k16.row.col.f32.bf16.bf16.f32 "
        "{%0,%1,%2,%3}, {%4,%5,%6,%7}, {%8,%9}, {%0,%1,%2,%3};"
        : "+f"(d[0]), "+f"(d[1]), "+f"(d[2]), "+f"(d[3])
        : "r"(a[0]), "r"(a[1]), "r"(a[2]), "r"(a[3]), "r"(b[0]), "r"(b[1]));
}
__device__ __forceinline__ void ldsm_x4(uint32_t* r, uint32_t addr) {
    asm volatile("ldmatrix.sync.aligned.m8n8.x4.shared.b16 {%0,%1,%2,%3}, [%4];"
        : "=r"(r[0]), "=r"(r[1]), "=r"(r[2]), "=r"(r[3]) : "r"(addr));
}
__device__ __forceinline__ uint32_t smem_to_u32(const void* p) {
    uint32_t a;
    asm("{ .reg .u64 t; cvta.to.shared.u64 t, %1; cvt.u32.u64 %0, t; }" : "=r"(a) : "l"(p));
    return a;
}
__device__ __forceinline__ void cp16(uint32_t s, const void* g) {
    asm volatile("cp.async.cg.shared.global [%0], [%1], 16;" :: "r"(s), "l"(g));
}
#define CP_COMMIT() asm volatile("cp.async.commit_group;" ::: "memory")
#define CP_WAIT(N)  asm volatile("cp.async.wait_group %0;" :: "n"(N) : "memory")

__device__ __forceinline__ void packsplit(float a, float b, uint32_t& hi, uint32_t& lo) {
    __nv_bfloat162 h = __floats2bfloat162_rn(a, b);
    hi = *(uint32_t*)&h;
    float ra = a - __bfloat162float(h.x);
    float rb = b - __bfloat162float(h.y);
    __nv_bfloat162 l = __floats2bfloat162_rn(ra, rb);
    lo = *(uint32_t*)&l;
}
__device__ __forceinline__ uint32_t pack_bf2(float a, float b) {
    __nv_bfloat162 p = __floats2bfloat162_rn(a, b);
    return *(uint32_t*)&p;
}
__device__ __forceinline__ uint32_t prmt(uint32_t a, uint32_t b, uint32_t sel) {
    uint32_t d;
    asm("prmt.b32 %0, %1, %2, %3;" : "=r"(d) : "r"(a), "r"(b), "r"(sel));
    return d;
}
__device__ __forceinline__ uint32_t mul_bf2(uint32_t a, uint32_t b) {
    uint32_t d;
    asm("mul.rn.bf16x2 %0, %1, %2;" : "=r"(d) : "r"(a), "r"(b));
    return d;
}
__device__ __forceinline__ uint32_t max_bf2(uint32_t a, uint32_t b) {
    uint32_t d;
    asm("max.bf16x2 %0, %1, %2;" : "=r"(d) : "r"(a), "r"(b));
    return d;
}

// ---------------------------------------------------------------- scratch
#define SCR_FLOATS (NN*DD + 2*HH*NN + HH*NN + 2*NN + NN + 16*NN*DD + 16*NN)
__device__ __align__(16) float g_scratch[SCR_FLOATS];
__device__ __align__(16) unsigned g_bits[NN*(NN/32)];
#define BF_ELEMS (2*NN*FF + 2*HH*FF*DD + 2*NN*FF + 2*NN*FF + 2*FF*DD + 2*NN*DD)
__device__ __align__(16) __nv_bfloat16 g_bf[BF_ELEMS];

// ---------------- prep: split x (z=0) + transpose/split W, Wo (z=1) ----------------
__global__ __launch_bounds__(256) void k_prep(
    const float* __restrict__ x, const float* __restrict__ W, const float* __restrict__ Wo,
    __nv_bfloat16* __restrict__ x_hi, __nv_bfloat16* __restrict__ x_lo,
    __nv_bfloat16* __restrict__ Wt_hi, __nv_bfloat16* __restrict__ Wt_lo,
    __nv_bfloat16* __restrict__ Wot_hi, __nv_bfloat16* __restrict__ Wot_lo)
{
    __shared__ float tile[32][33];
    int t = threadIdx.x;
    if (blockIdx.z == 0) {
        int i = blockIdx.x*256 + t;
        if (i >= NN*FF/4) return;
        float4 v = *(const float4*)(x + (size_t)i*4);
        uint32_t h0, l0, h1, l1;
        packsplit(v.x, v.y, h0, l0);
        packsplit(v.z, v.w, h1, l1);
        *(uint32_t*)(x_hi + (size_t)i*4)     = h0;
        *(uint32_t*)(x_hi + (size_t)i*4 + 2) = h1;
        *(uint32_t*)(x_lo + (size_t)i*4)     = l0;
        *(uint32_t*)(x_lo + (size_t)i*4 + 2) = l1;
        return;
    }
    const float* A; __nv_bfloat16 *Thi, *Tlo;
    int bxx, byy;
    int bx = blockIdx.x;
    if (bx < 256) {
        int h = bx >> 5, rem = bx & 31;
        bxx = rem & 15; byy = rem >> 4;
        A = W + (size_t)h*FF*DD;
        Thi = Wt_hi + (size_t)h*FF*DD;
        Tlo = Wt_lo + (size_t)h*FF*DD;
    } else if (bx < 288) {
        int idx = bx - 256;
        bxx = idx & 15; byy = idx >> 4;
        A = Wo; Thi = Wot_hi; Tlo = Wot_lo;
    } else return;
    int n0 = bxx*32, c0 = byy*32;
    int tx = t & 31, ty = t >> 5;
    #pragma unroll
    for (int i = 0; i < 4; i++) {
        int nr = ty*4 + i;
        tile[nr][tx] = A[(size_t)(n0+nr)*DD + c0 + tx];
    }
    __syncthreads();
    #pragma unroll
    for (int i = 0; i < 4; i++) {
        int cr = ty*4 + i;
        float v = tile[tx][cr];
        __nv_bfloat16 h = __float2bfloat16(v);
        Thi[(size_t)(c0+cr)*FF + n0 + tx] = h;
        Tlo[(size_t)(c0+cr)*FF + n0 + tx] = __float2bfloat16(v - __bfloat162float(h));
    }
}

// ---------------- adj -> bitmask ----------------
__global__ void k_bits(const int* __restrict__ adj, unsigned* __restrict__ bits) {
    int gw = (blockIdx.x * blockDim.x + threadIdx.x) >> 5;
    int lane = threadIdx.x & 31;
    if (gw >= NN*(NN/32)) return;
    int v = adj[(size_t)gw*32 + lane];
    unsigned b = __ballot_sync(0xFFFFFFFFu, v > 0);
    if (lane == 0) bits[gw] = b;
}

// ---------------- gemm1: fused HMMA GEMM + fexp + transposed split epilogue ----------------
#define G_AH 0
#define G_AL 18432
#define G_BH 36864
#define G_BL 46080
#define G_STAGE 55296
#define SMEM_G (2*G_STAGE)

__global__ __launch_bounds__(256, 2) void k_gemm_f(
    const __nv_bfloat16* __restrict__ Ah, const __nv_bfloat16* __restrict__ Al,
    const __nv_bfloat16* __restrict__ Bh, const __nv_bfloat16* __restrict__ Bl, int K,
    const float* __restrict__ av_src, const float* __restrict__ av_dst,
    float* __restrict__ Ap, float* __restrict__ An, uint32_t* __restrict__ pk,
    __nv_bfloat16* __restrict__ outT_hi, __nv_bfloat16* __restrict__ outT_lo)
{
    extern __shared__ char smem[];
    uint32_t sb = smem_to_u32(smem);
    int t = threadIdx.x;
    int wid = t >> 5, lane = t & 31;
    int n0 = blockIdx.x*128, c0 = blockIdx.y*64;
    int fbase = blockIdx.y*NN;
    float acc[8][4];
    #pragma unroll
    for (int i = 0; i < 8; i++)
        #pragma unroll
        for (int j = 0; j < 4; j++) acc[i][j] = 0.f;

    int mrow = wid*16 + (lane&7) + ((lane>>3)&1)*8;
    uint32_t aOff = (uint32_t)(mrow*72 + (lane>>4)*8)*2;
    uint32_t bOff = (uint32_t)((lane&7)*72 + (lane>>3)*8)*2;

    int chunks = K/64;
    auto stage = [&](int kc) {
        uint32_t dst = sb + (uint32_t)(kc & 1)*G_STAGE;
        int k0 = kc*64;
        #pragma unroll
        for (int i = 0; i < 4; i++) {
            int idx = t + i*256;
            int row = idx >> 3, k16 = idx & 7;
            cp16(dst + G_AH + row*144 + k16*16, Ah + (size_t)(n0+row)*K + k0 + k16*8);
            cp16(dst + G_AL + row*144 + k16*16, Al + (size_t)(n0+row)*K + k0 + k16*8);
        }
        #pragma unroll
        for (int i = 0; i < 2; i++) {
            int idx = t + i*256;
            int col = idx >> 3, k16 = idx & 7;
            cp16(dst + G_BH + col*144 + k16*16, Bh + (size_t)(c0+col)*K + k0 + k16*8);
            cp16(dst + G_BL + col*144 + k16*16, Bl + (size_t)(c0+col)*K + k0 + k16*8);
        }
        CP_COMMIT();
    };

    stage(0);
    for (int kc = 0; kc < chunks; kc++) {
        if (kc + 1 < chunks) { stage(kc + 1); CP_WAIT(1); }
        else                 { CP_WAIT(0); }
        __syncthreads();
        uint32_t sbuf = sb + (uint32_t)(kc & 1)*G_STAGE;
        #pragma unroll
        for (int ko = 0; ko < 2; ko++) {
            uint32_t ah[8], al[8];
            ldsm_x4(ah+0, sbuf + G_AH + aOff + ko*64);
            ldsm_x4(ah+4, sbuf + G_AH + aOff + ko*64 + 32);
            ldsm_x4(al+0, sbuf + G_AL + aOff + ko*64);
            ldsm_x4(al+4, sbuf + G_AL + aOff + ko*64 + 32);
            #pragma unroll
            for (int dt = 0; dt < 8; dt++) {
                uint32_t bh[4], bl[4];
                ldsm_x4(bh, sbuf + G_BH + bOff + dt*1152 + ko*64);
                ldsm_x4(bl, sbuf + G_BL + bOff + dt*1152 + ko*64);
                mma_bf16(acc[dt], ah+0, bh+0);
                mma_bf16(acc[dt], ah+4, bh+2);
                mma_bf16(acc[dt], ah+0, bl+0);
                mma_bf16(acc[dt], ah+4, bl+2);
                mma_bf16(acc[dt], al+0, bh+0);
                mma_bf16(acc[dt], al+4, bh+2);
            }
        }
        __syncthreads();
    }

    int qr = lane >> 2, c2 = (lane & 3)*2;
    int r0 = wid*16 + qr, r1 = r0 + 8;

    float fs0 = 0.f, fs1 = 0.f, fd0 = 0.f, fd1 = 0.f;
    #pragma unroll
    for (int dt = 0; dt < 8; dt++) {
        float a0 = av_src[c0 + dt*8 + c2], a1 = av_src[c0 + dt*8 + c2 + 1];
        float b0 = av_dst[c0 + dt*8 + c2], b1 = av_dst[c0 + dt*8 + c2 + 1];
        fs0 += acc[dt][0]*a0 + acc[dt][1]*a1;
        fs1 += acc[dt][2]*a0 + acc[dt][3]*a1;
        fd0 += acc[dt][0]*b0 + acc[dt][1]*b1;
        fd1 += acc[dt][2]*b0 + acc[dt][3]*b1;
    }
    #pragma unroll
    for (int o = 1; o <= 2; o <<= 1) {
        fs0 += __shfl_xor_sync(0xFFFFFFFFu, fs0, o);
        fs1 += __shfl_xor_sync(0xFFFFFFFFu, fs1, o);
        fd0 += __shfl_xor_sync(0xFFFFFFFFu, fd0, o);
        fd1 += __shfl_xor_sync(0xFFFFFFFFu, fd1, o);
    }
    if ((lane & 3) == 0) {
        int na = fbase + n0 + r0, nb = fbase + n0 + r1;
        Ap[na] = expf(fs0); An[na] = expf(0.2f*fs0);
        pk[na] = pack_bf2(expf(fd0), expf(0.2f*fd0));
        Ap[nb] = expf(fs1); An[nb] = expf(0.2f*fs1);
        pk[nb] = pack_bf2(expf(fd1), expf(0.2f*fd1));
    }

    float* sT = (float*)smem;
    #pragma unroll
    for (int dt = 0; dt < 8; dt++) {
        int c = dt*8 + c2;
        sT[(c  )*132 + r0] = acc[dt][0];
        sT[(c+1)*132 + r0] = acc[dt][1];
        sT[(c  )*132 + r1] = acc[dt][2];
        sT[(c+1)*132 + r1] = acc[dt][3];
    }
    __syncthreads();
    {
        int c = t >> 2;
        int nb = (t & 3)*32;
        const float* src = sT + c*132 + nb;
        __nv_bfloat16* dh = outT_hi + (size_t)(c0 + c)*NN + n0 + nb;
        __nv_bfloat16* dl = outT_lo + (size_t)(c0 + c)*NN + n0 + nb;
        #pragma unroll
        for (int j = 0; j < 16; j++) {
            uint32_t hi, lo;
            packsplit(src[j*2], src[j*2+1], hi, lo);
            *(uint32_t*)(dh + j*2) = hi;
            *(uint32_t*)(dl + j*2) = lo;
        }
    }
}

// ---------------- gemm2 part: 128-row x 64-col x K=128 slice -> fp32 partials ----------------
__global__ __launch_bounds__(256, 2) void k_gemm2_part(
    const __nv_bfloat16* __restrict__ Ah, const __nv_bfloat16* __restrict__ Al,
    const __nv_bfloat16* __restrict__ Bh, const __nv_bfloat16* __restrict__ Bl,
    float* __restrict__ gpart)
{
    extern __shared__ char smem[];
    uint32_t sb = smem_to_u32(smem);
    int t = threadIdx.x;
    int wid = t >> 5, lane = t & 31;
    int n0 = blockIdx.x*128;
    int seg = blockIdx.y;
    const int K = FF;
    float acc[8][4];
    #pragma unroll
    for (int i = 0; i < 8; i++)
        #pragma unroll
        for (int j = 0; j < 4; j++) acc[i][j] = 0.f;

    int mrow = wid*16 + (lane&7) + ((lane>>3)&1)*8;
    uint32_t aOff = (uint32_t)(mrow*72 + (lane>>4)*8)*2;
    uint32_t bOff = (uint32_t)((lane&7)*72 + (lane>>3)*8)*2;

    auto stage = [&](int kc) {
        uint32_t dst = sb + (uint32_t)(kc & 1)*G_STAGE;
        int k0 = seg*128 + kc*64;
        #pragma unroll
        for (int i = 0; i < 4; i++) {
            int idx = t + i*256;
            int row = idx >> 3, k16 = idx & 7;
            cp16(dst + G_AH + row*144 + k16*16, Ah + (size_t)(n0+row)*K + k0 + k16*8);
            cp16(dst + G_AL + row*144 + k16*16, Al + (size_t)(n0+row)*K + k0 + k16*8);
        }
        #pragma unroll
        for (int i = 0; i < 2; i++) {
            int idx = t + i*256;
            int col = idx >> 3, k16 = idx & 7;
            cp16(dst + G_BH + col*144 + k16*16, Bh + (size_t)col*K + k0 + k16*8);
            cp16(dst + G_BL + col*144 + k16*16, Bl + (size_t)col*K + k0 + k16*8);
        }
        CP_COMMIT();
    };

    stage(0);
    #pragma unroll
    for (int kc = 0; kc < 2; kc++) {
        if (kc == 0) { stage(1); CP_WAIT(1); }
        else         { CP_WAIT(0); }
        __syncthreads();
        uint32_t sbuf = sb + (uint32_t)(kc & 1)*G_STAGE;
        #pragma unroll
        for (int ko = 0; ko < 2; ko++) {
            uint32_t ah[8], al[8];
            ldsm_x4(ah+0, sbuf + G_AH + aOff + ko*64);
            ldsm_x4(ah+4, sbuf + G_AH + aOff + ko*64 + 32);
            ldsm_x4(al+0, sbuf + G_AL + aOff + ko*64);
            ldsm_x4(al+4, sbuf + G_AL + aOff + ko*64 + 32);
            #pragma unroll
            for (int dt = 0; dt < 8; dt++) {
                uint32_t bh[4], bl[4];
                ldsm_x4(bh, sbuf + G_BH + bOff + dt*1152 + ko*64);
                ldsm_x4(bl, sbuf + G_BL + bOff + dt*1152 + ko*64);
                mma_bf16(acc[dt], ah+0, bh+0);
                mma_bf16(acc[dt], ah+4, bh+2);
                mma_bf16(acc[dt], ah+0, bl+0);
                mma_bf16(acc[dt], ah+4, bl+2);
                mma_bf16(acc[dt], al+0, bh+0);
                mma_bf16(acc[dt], al+4, bh+2);
            }
        }
        __syncthreads();
    }

    int qr = lane >> 2, c2 = (lane & 3)*2;
    int r0 = wid*16 + qr, r1 = r0 + 8;
    float* p0 = gpart + ((size_t)seg*NN + n0 + r0)*64;
    float* p1 = gpart + ((size_t)seg*NN + n0 + r1)*64;
    #pragma unroll
    for (int dt = 0; dt < 8; dt++) {
        *(float2*)(p0 + dt*8 + c2) = make_float2(acc[dt][0], acc[dt][1]);
        *(float2*)(p1 + dt*8 + c2) = make_float2(acc[dt][2], acc[dt][3]);
    }
}

// ---------------- gemm2 finish: sum 4 partials + fexp + transposed split (hi only) ----------------
__global__ __launch_bounds__(256) void k_gemm2_fin(
    const float* __restrict__ gpart,
    const float* __restrict__ av_src, const float* __restrict__ av_dst,
    float* __restrict__ Ap, float* __restrict__ An, uint32_t* __restrict__ pk,
    __nv_bfloat16* __restrict__ outT_hi)
{
    extern __shared__ char smem[];
    int t = threadIdx.x;
    int wid = t >> 5, lane = t & 31;
    int n0 = blockIdx.x*128;
    int qr = lane >> 2, c2 = (lane & 3)*2;
    int r0 = wid*16 + qr, r1 = r0 + 8;

    float acc[8][4];
    #pragma unroll
    for (int i = 0; i < 8; i++)
        #pragma unroll
        for (int j = 0; j < 4; j++) acc[i][j] = 0.f;
    #pragma unroll
    for (int seg = 0; seg < 4; seg++) {
        const float* p0 = gpart + ((size_t)seg*NN + n0 + r0)*64;
        const float* p1 = gpart + ((size_t)seg*NN + n0 + r1)*64;
        #pragma unroll
        for (int dt = 0; dt < 8; dt++) {
            float2 v0 = *(const float2*)(p0 + dt*8 + c2);
            float2 v1 = *(const float2*)(p1 + dt*8 + c2);
            acc[dt][0] += v0.x; acc[dt][1] += v0.y;
            acc[dt][2] += v1.x; acc[dt][3] += v1.y;
        }
    }

    float fs0 = 0.f, fs1 = 0.f, fd0 = 0.f, fd1 = 0.f;
    #pragma unroll
    for (int dt = 0; dt < 8; dt++) {
        float a0 = av_src[dt*8 + c2], a1 = av_src[dt*8 + c2 + 1];
        float b0 = av_dst[dt*8 + c2], b1 = av_dst[dt*8 + c2 + 1];
        fs0 += acc[dt][0]*a0 + acc[dt][1]*a1;
        fs1 += acc[dt][2]*a0 + acc[dt][3]*a1;
        fd0 += acc[dt][0]*b0 + acc[dt][1]*b1;
        fd1 += acc[dt][2]*b0 + acc[dt][3]*b1;
    }
    #pragma unroll
    for (int o = 1; o <= 2; o <<= 1) {
        fs0 += __shfl_xor_sync(0xFFFFFFFFu, fs0, o);
        fs1 += __shfl_xor_sync(0xFFFFFFFFu, fs1, o);
        fd0 += __shfl_xor_sync(0xFFFFFFFFu, fd0, o);
        fd1 += __shfl_xor_sync(0xFFFFFFFFu, fd1, o);
    }
    if ((lane & 3) == 0) {
        int na = n0 + r0, nb = n0 + r1;
        Ap[na] = expf(fs0); An[na] = expf(0.2f*fs0);
        pk[na] = pack_bf2(expf(fd0), expf(0.2f*fd0));
        Ap[nb] = expf(fs1); An[nb] = expf(0.2f*fs1);
        pk[nb] = pack_bf2(expf(fd1), expf(0.2f*fd1));
    }

    float* sT = (float*)smem;
    #pragma unroll
    for (int dt = 0; dt < 8; dt++) {
        int c = dt*8 + c2;
        sT[(c  )*132 + r0] = acc[dt][0];
        sT[(c+1)*132 + r0] = acc[dt][1];
        sT[(c  )*132 + r1] = acc[dt][2];
        sT[(c+1)*132 + r1] = acc[dt][3];
    }
    __syncthreads();
    {
        int c = t >> 2;
        int nb = (t & 3)*32;
        const float* src = sT + c*132 + nb;
        __nv_bfloat16* dh = outT_hi + (size_t)c*NN + n0 + nb;
        #pragma unroll
        for (int j = 0; j < 16; j++) {
            *(uint32_t*)(dh + j*2) = pack_bf2(src[j*2], src[j*2+1]);
        }
    }
}

// ------------- attn: 128-thread CTAs (3/SM), 128-row tile, 128-m chunks, 3-stage, V hi-only -------------
// always writes fp32 partials (num to pnum, den to pden) at sidx = head*gridDim.z + seg
__global__ __launch_bounds__(128, 3) void k_attn_mma(
    const __nv_bfloat16* __restrict__ VT_hi,
    const float* __restrict__ Ap, const float* __restrict__ An,
    const uint32_t* __restrict__ pk,
    const unsigned* __restrict__ bits,
    int mPerCta, float* __restrict__ pnum, float* __restrict__ pden)
{
    constexpr uint32_t VH_OFF = 0;
    constexpr uint32_t PK_OFF = 17408u;
    constexpr uint32_t STAGE_B = 17920u;

    extern __shared__ char smem[];
    uint32_t sb = smem_to_u32(smem);
    int t = threadIdx.x;
    int wid = t >> 5, lane = t & 31;
    int head = blockIdx.y;
    int seg = blockIdx.z;
    int sidx = head * gridDim.z + seg;
    int n0 = blockIdx.x * 128;
    int fbase = head * NN;
    int coloff = head * 64;
    int mStart = seg * mPerCta;
    int iters = mPerCta / 128;

    int qr = lane >> 2;
    int c2 = (lane & 3) * 2;
    int rbase = n0 + wid*32;

    uint32_t Ap2[2][2], An2[2][2];
    const unsigned* brow[2][2];
    #pragma unroll
    for (int g = 0; g < 2; g++)
        #pragma unroll
        for (int s = 0; s < 2; s++) {
            int r = rbase + g*16 + s*8 + qr;
            float ap = Ap[fbase + r], an = An[fbase + r];
            Ap2[g][s] = pack_bf2(ap, ap);
            An2[g][s] = pack_bf2(an, an);
            brow[g][s] = bits + (size_t)r*(NN/32);
        }

    float acc[2][8][4];
    float accD[2][4];
    #pragma unroll
    for (int g = 0; g < 2; g++) {
        #pragma unroll
        for (int i = 0; i < 8; i++)
            #pragma unroll
            for (int j = 0; j < 4; j++) acc[g][i][j] = 0.f;
        #pragma unroll
        for (int j = 0; j < 4; j++) accD[g][j] = 0.f;
    }

    const uint32_t ones2[2] = {0x3F803F80u, 0x3F803F80u};

    auto stage = [&](int it) {
        uint32_t dst = sb + (uint32_t)(it % 3)*STAGE_B;
        int m0 = mStart + it*128;
        #pragma unroll
        for (int i = 0; i < 8; i++) {
            int idx = t + i*128;
            int d = idx >> 4, k16 = idx & 15;
            cp16(dst + VH_OFF + d*272 + k16*16, VT_hi + (size_t)(coloff + d)*NN + m0 + k16*8);
        }
        if (t < 32) cp16(dst + PK_OFF + t*16, pk + fbase + m0 + t*4);
        CP_COMMIT();
    };

    stage(0);
    if (iters > 1) stage(1);
    uint32_t bOff = (uint32_t)((lane & 7)*272 + (lane >> 3)*16);

    for (int it = 0; it < iters; it++) {
        if (it + 2 < iters)      { stage(it + 2); CP_WAIT(2); }
        else if (it + 1 < iters) { CP_WAIT(1); }
        else                     { CP_WAIT(0); }
        __syncthreads();

        int buf = it % 3;
        uint32_t sbuf = sb + (uint32_t)buf*STAGE_B;
        const uint32_t* pks = (const uint32_t*)(smem + buf*STAGE_B + PK_OFF);
        int m0 = mStart + it*128;

        unsigned bw[2][2][4];
        uint32_t tsh[2][2][4][2];
        #pragma unroll
        for (int g = 0; g < 2; g++)
            #pragma unroll
            for (int s = 0; s < 2; s++) {
                *(uint4*)bw[g][s] = *(const uint4*)(brow[g][s] + (m0 >> 5));
                #pragma unroll
                for (int wi = 0; wi < 4; wi++) {
                    tsh[g][s][wi][0] = bw[g][s][wi] << (7 - c2);
                    tsh[g][s][wi][1] = bw[g][s][wi] << (6 - c2);
                }
            }

        #pragma unroll
        for (int half = 0; half < 2; half++) {
            uint32_t ah[2][4][4];
            #pragma unroll
            for (int kc = 0; kc < 4; kc++) {
                int mloc = half*64 + kc*16;
                int mA = mloc + c2, mB = mA + 8;
                uint2 pa = *(const uint2*)(pks + mA);
                uint2 pb = *(const uint2*)(pks + mB);
                uint32_t BpA = prmt(pa.x, pa.y, 0x5410u), BnA = prmt(pa.x, pa.y, 0x7632u);
                uint32_t BpB = prmt(pb.x, pb.y, 0x5410u), BnB = prmt(pb.x, pb.y, 0x7632u);
                int wi = 2*half + (kc >> 1);
                uint32_t selA = (kc & 1) ? 0xEEAAu : 0xCC88u;
                uint32_t selB = (kc & 1) ? 0xFFBBu : 0xDD99u;
                #pragma unroll
                for (int g = 0; g < 2; g++) {
                    #pragma unroll
                    for (int s = 0; s < 2; s++) {
                        uint32_t ta = tsh[g][s][wi][0];
                        uint32_t tb = tsh[g][s][wi][1];
                        uint32_t maskA = prmt(ta, tb, selA);
                        uint32_t maskB = prmt(ta, tb, selB);
                        uint32_t wA = max_bf2(mul_bf2(Ap2[g][s], BpA),
                                              mul_bf2(An2[g][s], BnA)) & maskA;
                        uint32_t wB = max_bf2(mul_bf2(Ap2[g][s], BpB),
                                              mul_bf2(An2[g][s], BnB)) & maskB;
                        ah[g][kc][s]     = wA;
                        ah[g][kc][s + 2] = wB;
                    }
                }
            }
            #pragma unroll
            for (int ko = 0; ko < 2; ko++) {
                #pragma unroll
                for (int g = 0; g < 2; g++) {
                    mma_bf16(accD[g], ah[g][2*ko],   ones2);
                    mma_bf16(accD[g], ah[g][2*ko+1], ones2);
                }
                #pragma unroll
                for (int dt = 0; dt < 8; dt++) {
                    uint32_t bh[4];
                    ldsm_x4(bh, sbuf + VH_OFF + bOff + dt*2176 + (half*2+ko)*64);
                    #pragma unroll
                    for (int g = 0; g < 2; g++) {
                        mma_bf16(acc[g][dt], ah[g][2*ko],   bh+0);
                        mma_bf16(acc[g][dt], ah[g][2*ko+1], bh+2);
                    }
                }
            }
        }
        __syncthreads();
    }

    if ((lane & 3) == 0) {
        #pragma unroll
        for (int g = 0; g < 2; g++) {
            pden[(size_t)sidx*NN + rbase + g*16 + qr]     = accD[g][0];
            pden[(size_t)sidx*NN + rbase + g*16 + 8 + qr] = accD[g][2];
        }
    }
    #pragma unroll
    for (int g = 0; g < 2; g++) {
        float* p0 = pnum + ((size_t)sidx*NN + rbase + g*16 + qr)*64;
        float* p1 = pnum + ((size_t)sidx*NN + rbase + g*16 + 8 + qr)*64;
        #pragma unroll
        for (int dt = 0; dt < 8; dt++) {
            *(float2*)(p0 + dt*8 + c2) = make_float2(acc[g][dt][0], acc[g][dt][1]);
            *(float2*)(p1 + dt*8 + c2) = make_float2(acc[g][dt][2], acc[g][dt][3]);
        }
    }
}

// ------------- combine main-attn partials -> hcat hi/lo (divide + ELU + split) -------------
__global__ void k_comb_main(const float* __restrict__ pnum, const float* __restrict__ pden,
                            __nv_bfloat16* __restrict__ hc_hi, __nv_bfloat16* __restrict__ hc_lo)
{
    int gw = (blockIdx.x*blockDim.x + threadIdx.x) >> 5;
    int lane = threadIdx.x & 31;
    if (gw >= HH*NN) return;
    int h = gw >> 12, n = gw & (NN-1);
    int s0 = h*SPLITM;
    float den = 0.f;
    #pragma unroll
    for (int s = 0; s < SPLITM; s++) den += pden[(size_t)(s0+s)*NN + n];
    float inv = 1.0f / den;
    float2 a = make_float2(0.f, 0.f);
    #pragma unroll
    for (int s = 0; s < SPLITM; s++) {
        float2 v = ((const float2*)(pnum + ((size_t)(s0+s)*NN + n)*64))[lane];
        a.x += v.x; a.y += v.y;
    }
    float z0 = a.x*inv, z1 = a.y*inv;
    z0 = (z0 > 0.f) ? z0 : expm1f(z0);
    z1 = (z1 > 0.f) ? z1 : expm1f(z1);
    uint32_t hi, lo;
    packsplit(z0, z1, hi, lo);
    size_t o = (size_t)n*FF + h*64 + lane*2;
    *(uint32_t*)(hc_hi + o) = hi;
    *(uint32_t*)(hc_lo + o) = lo;
}

// ------------- combine out-head partials -> h2 -------------
__global__ void k_comb_out(const float* __restrict__ pnum, const float* __restrict__ pden,
                           float* __restrict__ h2)
{
    int gw = (blockIdx.x*blockDim.x + threadIdx.x) >> 5;
    int lane = threadIdx.x & 31;
    if (gw >= NN) return;
    float den = 0.f;
    #pragma unroll
    for (int s = 0; s < SPLITO; s++) den += pden[(size_t)s*NN + gw];
    float a0 = 0.f, a1 = 0.f;
    #pragma unroll
    for (int s = 0; s < SPLITO; s++) {
        const float* p = pnum + ((size_t)s*NN + gw)*64;
        a0 += p[lane]; a1 += p[lane+32];
    }
    float inv = 1.0f / den;
    h2[(size_t)gw*64 + lane]      = a0*inv;
    h2[(size_t)gw*64 + lane + 32] = a1*inv;
}

// ------------- ELU + row log_softmax -------------
__global__ void k_final(const float* __restrict__ h2, float* __restrict__ out) {
    int gw = (blockIdx.x*blockDim.x + threadIdx.x) >> 5;
    int lane = threadIdx.x & 31;
    if (gw >= NN) return;
    const float* row = h2 + (size_t)gw*64;
    float z0 = row[lane], z1 = row[lane+32];
    z0 = (z0 > 0.f) ? z0 : expm1f(z0);
    z1 = (z1 > 0.f) ? z1 : expm1f(z1);
    float mx = fmaxf(z0, z1);
    #pragma unroll
    for (int o = 16; o; o >>= 1) mx = fmaxf(mx, __shfl_xor_sync(0xFFFFFFFFu, mx, o));
    float se = expf(z0 - mx) + expf(z1 - mx);
    #pragma unroll
    for (int o = 16; o; o >>= 1) se += __shfl_xor_sync(0xFFFFFFFFu, se, o);
    float lse = mx + logf(se);
    out[(size_t)gw*64 + lane]      = z0 - lse;
    out[(size_t)gw*64 + lane + 32] = z1 - lse;
}

extern "C" void kernel_launch(void* const* d_in, const int* in_sizes, int n_in,
                              void* d_out, int out_size)
{
    const float* x     = (const float*)d_in[0];
    const int*   adj   = (const int*)  d_in[1];
    const float* W     = (const float*)d_in[2];
    const float* asrc  = (const float*)d_in[3];
    const float* adst  = (const float*)d_in[4];
    const float* Wo    = (const float*)d_in[5];
    const float* aosrc = (const float*)d_in[6];
    const float* aodst = (const float*)d_in[7];
    float* out = (float*)d_out;

    void* sp = nullptr;  cudaGetSymbolAddress(&sp, g_scratch);
    void* bpv = nullptr; cudaGetSymbolAddress(&bpv, g_bits);
    void* bfv = nullptr; cudaGetSymbolAddress(&bfv, g_bf);
    float* S = (float*)sp;
    unsigned* bits = (unsigned*)bpv;
    __nv_bfloat16* BF = (__nv_bfloat16*)bfv;

    float* h2     = S;
    float* ApM    = h2  + (size_t)NN*DD;
    float* AnM    = ApM + (size_t)HH*NN;
    uint32_t* pkM = (uint32_t*)(AnM + (size_t)HH*NN);
    float* ApO    = (float*)(pkM + (size_t)HH*NN);
    float* AnO    = ApO + NN;
    uint32_t* pkO = (uint32_t*)(AnO + NN);
    float* pnum   = (float*)(pkO + NN);
    float* pden   = pnum + (size_t)16*NN*DD;
    float* gpart  = pnum;

    __nv_bfloat16* x_hi   = BF;
    __nv_bfloat16* x_lo   = x_hi   + (size_t)NN*FF;
    __nv_bfloat16* Wt_hi  = x_lo   + (size_t)NN*FF;
    __nv_bfloat16* Wt_lo  = Wt_hi  + (size_t)HH*FF*DD;
    __nv_bfloat16* WhT_hi = Wt_lo  + (size_t)HH*FF*DD;
    __nv_bfloat16* WhT_lo = WhT_hi + (size_t)NN*FF;
    __nv_bfloat16* hc_hi  = WhT_lo + (size_t)NN*FF;
    __nv_bfloat16* hc_lo  = hc_hi  + (size_t)NN*FF;
    __nv_bfloat16* Wot_hi = hc_lo  + (size_t)NN*FF;
    __nv_bfloat16* Wot_lo = Wot_hi + (size_t)FF*DD;
    __nv_bfloat16* WoT_hi = Wot_lo + (size_t)FF*DD;

    cudaFuncSetAttribute(k_gemm_f, cudaFuncAttributeMaxDynamicSharedMemorySize, SMEM_G);
    cudaFuncSetAttribute(k_gemm2_part, cudaFuncAttributeMaxDynamicSharedMemorySize, SMEM_G);
    cudaFuncSetAttribute(k_gemm2_fin, cudaFuncAttributeMaxDynamicSharedMemorySize, 64*132*4);
    cudaFuncSetAttribute(k_attn_mma, cudaFuncAttributeMaxDynamicSharedMemorySize, 3*17920);

    // 0) prep
    k_prep<<<dim3(2048, 1, 2), 256>>>(x, W, Wo, x_hi, x_lo, Wt_hi, Wt_lo, Wot_hi, Wot_lo);
    // 1) adj -> bitmask
    {
        long long threads = (long long)NN*(NN/32)*32;
        k_bits<<<(unsigned)((threads + 255)/256), 256>>>(adj, bits);
    }
    // 2) gemm1 fused
    k_gemm_f<<<dim3(NN/128, FF/64), 256, SMEM_G>>>(x_hi, x_lo, Wt_hi, Wt_lo, FF,
        asrc, adst, ApM, AnM, pkM, WhT_hi, WhT_lo);
    // 3) main attention: 2-way m-split, 512 CTAs -> partials
    k_attn_mma<<<dim3(NN/128, HH, SPLITM), 128, 3*17920>>>(WhT_hi,
        ApM, AnM, pkM, bits, NN/SPLITM, pnum, pden);
    // 3b) combine -> hcat hi/lo (divide + ELU + split)
    k_comb_main<<<(HH*NN*32 + 255)/256, 256>>>(pnum, pden, hc_hi, hc_lo);
    // 4) gemm2: 4-way K-split partials + finish
    k_gemm2_part<<<dim3(NN/128, 4), 256, SMEM_G>>>(hc_hi, hc_lo, Wot_hi, Wot_lo, gpart);
    k_gemm2_fin<<<NN/128, 256, 64*132*4>>>(gpart, aosrc, aodst, ApO, AnO, pkO, WoT_hi);
    // 5) out-head attention: 16-way m-split, 512 CTAs -> partials
    k_attn_mma<<<dim3(NN/128, 1, SPLITO), 128, 3*17920>>>(WoT_hi,
        ApO, AnO, pkO, bits, NN/SPLITO, pnum, pden);
    // 6) combine + 7) final
    k_comb_out<<<(NN*32 + 255)/256, 256>>>(pnum, pden, h2);
    k_final<<<(NN*32 + 255)/256, 256>>>(h2, out);
}

// round 17
// speedup vs baseline: 1.1624x; 1.1624x over previous
#include <cuda_runtime.h>
#include <cuda_bf16.h>
#include <cstdint>

#define NN 4096
#define FF 512
#define DD 64
#define HH 8
#define SPLIT 8

// ---------------------------------------------------------------- helpers
__device__ __forceinline__ void mma_bf16(float* d, const uint32_t* a, const uint32_t* b) {
    asm volatile("mma.sync.aligned.m16n8k16.row.col.f32.bf16.bf16.f32 "
        "{%0,%1,%2,%3}, {%4,%5,%6,%7}, {%8,%9}, {%0,%1,%2,%3};"
        : "+f"(d[0]), "+f"(d[1]), "+f"(d[2]), "+f"(d[3])
        : "r"(a[0]), "r"(a[1]), "r"(a[2]), "r"(a[3]), "r"(b[0]), "r"(b[1]));
}
__device__ __forceinline__ void ldsm_x4(uint32_t* r, uint32_t addr) {
    asm volatile("ldmatrix.sync.aligned.m8n8.x4.shared.b16 {%0,%1,%2,%3}, [%4];"
        : "=r"(r[0]), "=r"(r[1]), "=r"(r[2]), "=r"(r[3]) : "r"(addr));
}
__device__ __forceinline__ uint32_t smem_to_u32(const void* p) {
    uint32_t a;
    asm("{ .reg .u64 t; cvta.to.shared.u64 t, %1; cvt.u32.u64 %0, t; }" : "=r"(a) : "l"(p));
    return a;
}
__device__ __forceinline__ void cp16(uint32_t s, const void* g) {
    asm volatile("cp.async.cg.shared.global [%0], [%1], 16;" :: "r"(s), "l"(g));
}
#define CP_COMMIT() asm volatile("cp.async.commit_group;" ::: "memory")
#define CP_WAIT(N)  asm volatile("cp.async.wait_group %0;" :: "n"(N) : "memory")

__device__ __forceinline__ void packsplit(float a, float b, uint32_t& hi, uint32_t& lo) {
    __nv_bfloat162 h = __floats2bfloat162_rn(a, b);
    hi = *(uint32_t*)&h;
    float ra = a - __bfloat162float(h.x);
    float rb = b - __bfloat162float(h.y);
    __nv_bfloat162 l = __floats2bfloat162_rn(ra, rb);
    lo = *(uint32_t*)&l;
}
__device__ __forceinline__ uint32_t pack_bf2(float a, float b) {
    __nv_bfloat162 p = __floats2bfloat162_rn(a, b);
    return *(uint32_t*)&p;
}
__device__ __forceinline__ uint32_t prmt(uint32_t a, uint32_t b, uint32_t sel) {
    uint32_t d;
    asm("prmt.b32 %0, %1, %2, %3;" : "=r"(d) : "r"(a), "r"(b), "r"(sel));
    return d;
}
__device__ __forceinline__ uint32_t mul_bf2(uint32_t a, uint32_t b) {
    uint32_t d;
    asm("mul.rn.bf16x2 %0, %1, %2;" : "=r"(d) : "r"(a), "r"(b));
    return d;
}
__device__ __forceinline__ uint32_t max_bf2(uint32_t a, uint32_t b) {
    uint32_t d;
    asm("max.bf16x2 %0, %1, %2;" : "=r"(d) : "r"(a), "r"(b));
    return d;
}

// ---------------------------------------------------------------- scratch
#define SCR_FLOATS (NN*DD + 2*HH*NN + HH*NN + 2*NN + NN + SPLIT*NN*DD + SPLIT*NN)
__device__ __align__(16) float g_scratch[SCR_FLOATS];
__device__ __align__(16) unsigned g_bits[NN*(NN/32)];
#define BF_ELEMS (2*NN*FF + 2*HH*FF*DD + 2*NN*FF + 2*NN*FF + 2*FF*DD + 2*NN*DD)
__device__ __align__(16) __nv_bfloat16 g_bf[BF_ELEMS];

// ---------------- prep: split x (z=0) + transpose/split W,Wo (z=1) + adj->bits (z=2) ----------------
__global__ __launch_bounds__(256) void k_prep(
    const float* __restrict__ x, const float* __restrict__ W, const float* __restrict__ Wo,
    __nv_bfloat16* __restrict__ x_hi, __nv_bfloat16* __restrict__ x_lo,
    __nv_bfloat16* __restrict__ Wt_hi, __nv_bfloat16* __restrict__ Wt_lo,
    __nv_bfloat16* __restrict__ Wot_hi, __nv_bfloat16* __restrict__ Wot_lo,
    const int* __restrict__ adj, unsigned* __restrict__ bits)
{
    __shared__ float tile[32][33];
    int t = threadIdx.x;
    if (blockIdx.z == 0) {
        int i = blockIdx.x*256 + t;
        if (i >= NN*FF/4) return;
        float4 v = *(const float4*)(x + (size_t)i*4);
        uint32_t h0, l0, h1, l1;
        packsplit(v.x, v.y, h0, l0);
        packsplit(v.z, v.w, h1, l1);
        *(uint32_t*)(x_hi + (size_t)i*4)     = h0;
        *(uint32_t*)(x_hi + (size_t)i*4 + 2) = h1;
        *(uint32_t*)(x_lo + (size_t)i*4)     = l0;
        *(uint32_t*)(x_lo + (size_t)i*4 + 2) = l1;
        return;
    }
    if (blockIdx.z == 2) {
        // adj -> bitmask, grid-strided over all 2048 blocks
        int lane = t & 31;
        int gwarp = blockIdx.x*8 + (t >> 5);            // 0..16383
        for (int w = gwarp; w < NN*(NN/32); w += 2048*8) {
            int v = adj[(size_t)w*32 + lane];
            unsigned b = __ballot_sync(0xFFFFFFFFu, v > 0);
            if (lane == 0) bits[w] = b;
        }
        return;
    }
    const float* A; __nv_bfloat16 *Thi, *Tlo;
    int bxx, byy;
    int bx = blockIdx.x;
    if (bx < 256) {
        int h = bx >> 5, rem = bx & 31;
        bxx = rem & 15; byy = rem >> 4;
        A = W + (size_t)h*FF*DD;
        Thi = Wt_hi + (size_t)h*FF*DD;
        Tlo = Wt_lo + (size_t)h*FF*DD;
    } else if (bx < 288) {
        int idx = bx - 256;
        bxx = idx & 15; byy = idx >> 4;
        A = Wo; Thi = Wot_hi; Tlo = Wot_lo;
    } else return;
    int n0 = bxx*32, c0 = byy*32;
    int tx = t & 31, ty = t >> 5;
    #pragma unroll
    for (int i = 0; i < 4; i++) {
        int nr = ty*4 + i;
        tile[nr][tx] = A[(size_t)(n0+nr)*DD + c0 + tx];
    }
    __syncthreads();
    #pragma unroll
    for (int i = 0; i < 4; i++) {
        int cr = ty*4 + i;
        float v = tile[tx][cr];
        __nv_bfloat16 h = __float2bfloat16(v);
        Thi[(size_t)(c0+cr)*FF + n0 + tx] = h;
        Tlo[(size_t)(c0+cr)*FF + n0 + tx] = __float2bfloat16(v - __bfloat162float(h));
    }
}

// ---------------- gemm1: fused HMMA GEMM + fexp + transposed split epilogue ----------------
#define G_AH 0
#define G_AL 18432
#define G_BH 36864
#define G_BL 46080
#define G_STAGE 55296
#define SMEM_G (2*G_STAGE)

__global__ __launch_bounds__(256, 2) void k_gemm_f(
    const __nv_bfloat16* __restrict__ Ah, const __nv_bfloat16* __restrict__ Al,
    const __nv_bfloat16* __restrict__ Bh, const __nv_bfloat16* __restrict__ Bl, int K,
    const float* __restrict__ av_src, const float* __restrict__ av_dst,
    float* __restrict__ Ap, float* __restrict__ An, uint32_t* __restrict__ pk,
    __nv_bfloat16* __restrict__ outT_hi, __nv_bfloat16* __restrict__ outT_lo)
{
    extern __shared__ char smem[];
    uint32_t sb = smem_to_u32(smem);
    int t = threadIdx.x;
    int wid = t >> 5, lane = t & 31;
    int n0 = blockIdx.x*128, c0 = blockIdx.y*64;
    int fbase = blockIdx.y*NN;
    float acc[8][4];
    #pragma unroll
    for (int i = 0; i < 8; i++)
        #pragma unroll
        for (int j = 0; j < 4; j++) acc[i][j] = 0.f;

    int mrow = wid*16 + (lane&7) + ((lane>>3)&1)*8;
    uint32_t aOff = (uint32_t)(mrow*72 + (lane>>4)*8)*2;
    uint32_t bOff = (uint32_t)((lane&7)*72 + (lane>>3)*8)*2;

    int chunks = K/64;
    auto stage = [&](int kc) {
        uint32_t dst = sb + (uint32_t)(kc & 1)*G_STAGE;
        int k0 = kc*64;
        #pragma unroll
        for (int i = 0; i < 4; i++) {
            int idx = t + i*256;
            int row = idx >> 3, k16 = idx & 7;
            cp16(dst + G_AH + row*144 + k16*16, Ah + (size_t)(n0+row)*K + k0 + k16*8);
            cp16(dst + G_AL + row*144 + k16*16, Al + (size_t)(n0+row)*K + k0 + k16*8);
        }
        #pragma unroll
        for (int i = 0; i < 2; i++) {
            int idx = t + i*256;
            int col = idx >> 3, k16 = idx & 7;
            cp16(dst + G_BH + col*144 + k16*16, Bh + (size_t)(c0+col)*K + k0 + k16*8);
            cp16(dst + G_BL + col*144 + k16*16, Bl + (size_t)(c0+col)*K + k0 + k16*8);
        }
        CP_COMMIT();
    };

    stage(0);
    for (int kc = 0; kc < chunks; kc++) {
        if (kc + 1 < chunks) { stage(kc + 1); CP_WAIT(1); }
        else                 { CP_WAIT(0); }
        __syncthreads();
        uint32_t sbuf = sb + (uint32_t)(kc & 1)*G_STAGE;
        #pragma unroll
        for (int ko = 0; ko < 2; ko++) {
            uint32_t ah[8], al[8];
            ldsm_x4(ah+0, sbuf + G_AH + aOff + ko*64);
            ldsm_x4(ah+4, sbuf + G_AH + aOff + ko*64 + 32);
            ldsm_x4(al+0, sbuf + G_AL + aOff + ko*64);
            ldsm_x4(al+4, sbuf + G_AL + aOff + ko*64 + 32);
            #pragma unroll
            for (int dt = 0; dt < 8; dt++) {
                uint32_t bh[4], bl[4];
                ldsm_x4(bh, sbuf + G_BH + bOff + dt*1152 + ko*64);
                ldsm_x4(bl, sbuf + G_BL + bOff + dt*1152 + ko*64);
                mma_bf16(acc[dt], ah+0, bh+0);
                mma_bf16(acc[dt], ah+4, bh+2);
                mma_bf16(acc[dt], ah+0, bl+0);
                mma_bf16(acc[dt], ah+4, bl+2);
                mma_bf16(acc[dt], al+0, bh+0);
                mma_bf16(acc[dt], al+4, bh+2);
            }
        }
        __syncthreads();
    }

    int qr = lane >> 2, c2 = (lane & 3)*2;
    int r0 = wid*16 + qr, r1 = r0 + 8;

    float fs0 = 0.f, fs1 = 0.f, fd0 = 0.f, fd1 = 0.f;
    #pragma unroll
    for (int dt = 0; dt < 8; dt++) {
        float a0 = av_src[c0 + dt*8 + c2], a1 = av_src[c0 + dt*8 + c2 + 1];
        float b0 = av_dst[c0 + dt*8 + c2], b1 = av_dst[c0 + dt*8 + c2 + 1];
        fs0 += acc[dt][0]*a0 + acc[dt][1]*a1;
        fs1 += acc[dt][2]*a0 + acc[dt][3]*a1;
        fd0 += acc[dt][0]*b0 + acc[dt][1]*b1;
        fd1 += acc[dt][2]*b0 + acc[dt][3]*b1;
    }
    #pragma unroll
    for (int o = 1; o <= 2; o <<= 1) {
        fs0 += __shfl_xor_sync(0xFFFFFFFFu, fs0, o);
        fs1 += __shfl_xor_sync(0xFFFFFFFFu, fs1, o);
        fd0 += __shfl_xor_sync(0xFFFFFFFFu, fd0, o);
        fd1 += __shfl_xor_sync(0xFFFFFFFFu, fd1, o);
    }
    if ((lane & 3) == 0) {
        int na = fbase + n0 + r0, nb = fbase + n0 + r1;
        Ap[na] = expf(fs0); An[na] = expf(0.2f*fs0);
        pk[na] = pack_bf2(expf(fd0), expf(0.2f*fd0));
        Ap[nb] = expf(fs1); An[nb] = expf(0.2f*fs1);
        pk[nb] = pack_bf2(expf(fd1), expf(0.2f*fd1));
    }

    float* sT = (float*)smem;
    #pragma unroll
    for (int dt = 0; dt < 8; dt++) {
        int c = dt*8 + c2;
        sT[(c  )*132 + r0] = acc[dt][0];
        sT[(c+1)*132 + r0] = acc[dt][1];
        sT[(c  )*132 + r1] = acc[dt][2];
        sT[(c+1)*132 + r1] = acc[dt][3];
    }
    __syncthreads();
    {
        int c = t >> 2;
        int nb = (t & 3)*32;
        const float* src = sT + c*132 + nb;
        __nv_bfloat16* dh = outT_hi + (size_t)(c0 + c)*NN + n0 + nb;
        __nv_bfloat16* dl = outT_lo + (size_t)(c0 + c)*NN + n0 + nb;
        #pragma unroll
        for (int j = 0; j < 16; j++) {
            uint32_t hi, lo;
            packsplit(src[j*2], src[j*2+1], hi, lo);
            *(uint32_t*)(dh + j*2) = hi;
            *(uint32_t*)(dl + j*2) = lo;
        }
    }
}

// ---------------- gemm2 part: 128-row x 64-col x K=128 slice -> fp32 partials ----------------
__global__ __launch_bounds__(256, 2) void k_gemm2_part(
    const __nv_bfloat16* __restrict__ Ah, const __nv_bfloat16* __restrict__ Al,
    const __nv_bfloat16* __restrict__ Bh, const __nv_bfloat16* __restrict__ Bl,
    float* __restrict__ gpart)
{
    extern __shared__ char smem[];
    uint32_t sb = smem_to_u32(smem);
    int t = threadIdx.x;
    int wid = t >> 5, lane = t & 31;
    int n0 = blockIdx.x*128;
    int seg = blockIdx.y;
    const int K = FF;
    float acc[8][4];
    #pragma unroll
    for (int i = 0; i < 8; i++)
        #pragma unroll
        for (int j = 0; j < 4; j++) acc[i][j] = 0.f;

    int mrow = wid*16 + (lane&7) + ((lane>>3)&1)*8;
    uint32_t aOff = (uint32_t)(mrow*72 + (lane>>4)*8)*2;
    uint32_t bOff = (uint32_t)((lane&7)*72 + (lane>>3)*8)*2;

    auto stage = [&](int kc) {
        uint32_t dst = sb + (uint32_t)(kc & 1)*G_STAGE;
        int k0 = seg*128 + kc*64;
        #pragma unroll
        for (int i = 0; i < 4; i++) {
            int idx = t + i*256;
            int row = idx >> 3, k16 = idx & 7;
            cp16(dst + G_AH + row*144 + k16*16, Ah + (size_t)(n0+row)*K + k0 + k16*8);
            cp16(dst + G_AL + row*144 + k16*16, Al + (size_t)(n0+row)*K + k0 + k16*8);
        }
        #pragma unroll
        for (int i = 0; i < 2; i++) {
            int idx = t + i*256;
            int col = idx >> 3, k16 = idx & 7;
            cp16(dst + G_BH + col*144 + k16*16, Bh + (size_t)col*K + k0 + k16*8);
            cp16(dst + G_BL + col*144 + k16*16, Bl + (size_t)col*K + k0 + k16*8);
        }
        CP_COMMIT();
    };

    stage(0);
    #pragma unroll
    for (int kc = 0; kc < 2; kc++) {
        if (kc == 0) { stage(1); CP_WAIT(1); }
        else         { CP_WAIT(0); }
        __syncthreads();
        uint32_t sbuf = sb + (uint32_t)(kc & 1)*G_STAGE;
        #pragma unroll
        for (int ko = 0; ko < 2; ko++) {
            uint32_t ah[8], al[8];
            ldsm_x4(ah+0, sbuf + G_AH + aOff + ko*64);
            ldsm_x4(ah+4, sbuf + G_AH + aOff + ko*64 + 32);
            ldsm_x4(al+0, sbuf + G_AL + aOff + ko*64);
            ldsm_x4(al+4, sbuf + G_AL + aOff + ko*64 + 32);
            #pragma unroll
            for (int dt = 0; dt < 8; dt++) {
                uint32_t bh[4], bl[4];
                ldsm_x4(bh, sbuf + G_BH + bOff + dt*1152 + ko*64);
                ldsm_x4(bl, sbuf + G_BL + bOff + dt*1152 + ko*64);
                mma_bf16(acc[dt], ah+0, bh+0);
                mma_bf16(acc[dt], ah+4, bh+2);
                mma_bf16(acc[dt], ah+0, bl+0);
                mma_bf16(acc[dt], ah+4, bl+2);
                mma_bf16(acc[dt], al+0, bh+0);
                mma_bf16(acc[dt], al+4, bh+2);
            }
        }
        __syncthreads();
    }

    int qr = lane >> 2, c2 = (lane & 3)*2;
    int r0 = wid*16 + qr, r1 = r0 + 8;
    float* p0 = gpart + ((size_t)seg*NN + n0 + r0)*64;
    float* p1 = gpart + ((size_t)seg*NN + n0 + r1)*64;
    #pragma unroll
    for (int dt = 0; dt < 8; dt++) {
        *(float2*)(p0 + dt*8 + c2) = make_float2(acc[dt][0], acc[dt][1]);
        *(float2*)(p1 + dt*8 + c2) = make_float2(acc[dt][2], acc[dt][3]);
    }
}

// ---------------- gemm2 finish: sum 4 partials + fexp + transposed split (hi only) ----------------
__global__ __launch_bounds__(256) void k_gemm2_fin(
    const float* __restrict__ gpart,
    const float* __restrict__ av_src, const float* __restrict__ av_dst,
    float* __restrict__ Ap, float* __restrict__ An, uint32_t* __restrict__ pk,
    __nv_bfloat16* __restrict__ outT_hi)
{
    extern __shared__ char smem[];
    int t = threadIdx.x;
    int wid = t >> 5, lane = t & 31;
    int n0 = blockIdx.x*128;
    int qr = lane >> 2, c2 = (lane & 3)*2;
    int r0 = wid*16 + qr, r1 = r0 + 8;

    float acc[8][4];
    #pragma unroll
    for (int i = 0; i < 8; i++)
        #pragma unroll
        for (int j = 0; j < 4; j++) acc[i][j] = 0.f;
    #pragma unroll
    for (int seg = 0; seg < 4; seg++) {
        const float* p0 = gpart + ((size_t)seg*NN + n0 + r0)*64;
        const float* p1 = gpart + ((size_t)seg*NN + n0 + r1)*64;
        #pragma unroll
        for (int dt = 0; dt < 8; dt++) {
            float2 v0 = *(const float2*)(p0 + dt*8 + c2);
            float2 v1 = *(const float2*)(p1 + dt*8 + c2);
            acc[dt][0] += v0.x; acc[dt][1] += v0.y;
            acc[dt][2] += v1.x; acc[dt][3] += v1.y;
        }
    }

    float fs0 = 0.f, fs1 = 0.f, fd0 = 0.f, fd1 = 0.f;
    #pragma unroll
    for (int dt = 0; dt < 8; dt++) {
        float a0 = av_src[dt*8 + c2], a1 = av_src[dt*8 + c2 + 1];
        float b0 = av_dst[dt*8 + c2], b1 = av_dst[dt*8 + c2 + 1];
        fs0 += acc[dt][0]*a0 + acc[dt][1]*a1;
        fs1 += acc[dt][2]*a0 + acc[dt][3]*a1;
        fd0 += acc[dt][0]*b0 + acc[dt][1]*b1;
        fd1 += acc[dt][2]*b0 + acc[dt][3]*b1;
    }
    #pragma unroll
    for (int o = 1; o <= 2; o <<= 1) {
        fs0 += __shfl_xor_sync(0xFFFFFFFFu, fs0, o);
        fs1 += __shfl_xor_sync(0xFFFFFFFFu, fs1, o);
        fd0 += __shfl_xor_sync(0xFFFFFFFFu, fd0, o);
        fd1 += __shfl_xor_sync(0xFFFFFFFFu, fd1, o);
    }
    if ((lane & 3) == 0) {
        int na = n0 + r0, nb = n0 + r1;
        Ap[na] = expf(fs0); An[na] = expf(0.2f*fs0);
        pk[na] = pack_bf2(expf(fd0), expf(0.2f*fd0));
        Ap[nb] = expf(fs1); An[nb] = expf(0.2f*fs1);
        pk[nb] = pack_bf2(expf(fd1), expf(0.2f*fd1));
    }

    float* sT = (float*)smem;
    #pragma unroll
    for (int dt = 0; dt < 8; dt++) {
        int c = dt*8 + c2;
        sT[(c  )*132 + r0] = acc[dt][0];
        sT[(c+1)*132 + r0] = acc[dt][1];
        sT[(c  )*132 + r1] = acc[dt][2];
        sT[(c+1)*132 + r1] = acc[dt][3];
    }
    __syncthreads();
    {
        int c = t >> 2;
        int nb = (t & 3)*32;
        const float* src = sT + c*132 + nb;
        __nv_bfloat16* dh = outT_hi + (size_t)c*NN + n0 + nb;
        #pragma unroll
        for (int j = 0; j < 16; j++) {
            *(uint32_t*)(dh + j*2) = pack_bf2(src[j*2], src[j*2+1]);
        }
    }
}

// ------------- attn: 128-thread CTAs (3/SM), 128-row tile, 128-m chunks, 3-stage, V hi-only -------------
__global__ __launch_bounds__(128, 3) void k_attn_mma(
    const __nv_bfloat16* __restrict__ VT_hi,
    const float* __restrict__ Ap, const float* __restrict__ An,
    const uint32_t* __restrict__ pk,
    const unsigned* __restrict__ bits,
    __nv_bfloat16* __restrict__ out_hi, __nv_bfloat16* __restrict__ out_lo, int ldout,
    int mPerCta, float* __restrict__ pnum, float* __restrict__ pden, int partial)
{
    constexpr uint32_t VH_OFF = 0;
    constexpr uint32_t PK_OFF = 17408u;
    constexpr uint32_t STAGE_B = 17920u;

    extern __shared__ char smem[];
    uint32_t sb = smem_to_u32(smem);
    int t = threadIdx.x;
    int wid = t >> 5, lane = t & 31;
    int head = blockIdx.y;
    int seg = blockIdx.z;
    int n0 = blockIdx.x * 128;
    int fbase = head * NN;
    int coloff = head * 64;
    int mStart = seg * mPerCta;
    int iters = mPerCta / 128;

    int qr = lane >> 2;
    int c2 = (lane & 3) * 2;
    int rbase = n0 + wid*32;

    uint32_t Ap2[2][2], An2[2][2];
    const unsigned* brow[2][2];
    #pragma unroll
    for (int g = 0; g < 2; g++)
        #pragma unroll
        for (int s = 0; s < 2; s++) {
            int r = rbase + g*16 + s*8 + qr;
            float ap = Ap[fbase + r], an = An[fbase + r];
            Ap2[g][s] = pack_bf2(ap, ap);
            An2[g][s] = pack_bf2(an, an);
            brow[g][s] = bits + (size_t)r*(NN/32);
        }

    float acc[2][8][4];
    float accD[2][4];
    #pragma unroll
    for (int g = 0; g < 2; g++) {
        #pragma unroll
        for (int i = 0; i < 8; i++)
            #pragma unroll
            for (int j = 0; j < 4; j++) acc[g][i][j] = 0.f;
        #pragma unroll
        for (int j = 0; j < 4; j++) accD[g][j] = 0.f;
    }

    const uint32_t ones2[2] = {0x3F803F80u, 0x3F803F80u};

    auto stage = [&](int it) {
        uint32_t dst = sb + (uint32_t)(it % 3)*STAGE_B;
        int m0 = mStart + it*128;
        #pragma unroll
        for (int i = 0; i < 8; i++) {
            int idx = t + i*128;
            int d = idx >> 4, k16 = idx & 15;
            cp16(dst + VH_OFF + d*272 + k16*16, VT_hi + (size_t)(coloff + d)*NN + m0 + k16*8);
        }
        if (t < 32) cp16(dst + PK_OFF + t*16, pk + fbase + m0 + t*4);
        CP_COMMIT();
    };

    stage(0);
    if (iters > 1) stage(1);
    uint32_t bOff = (uint32_t)((lane & 7)*272 + (lane >> 3)*16);

    for (int it = 0; it < iters; it++) {
        if (it + 2 < iters)      { stage(it + 2); CP_WAIT(2); }
        else if (it + 1 < iters) { CP_WAIT(1); }
        else                     { CP_WAIT(0); }
        __syncthreads();

        int buf = it % 3;
        uint32_t sbuf = sb + (uint32_t)buf*STAGE_B;
        const uint32_t* pks = (const uint32_t*)(smem + buf*STAGE_B + PK_OFF);
        int m0 = mStart + it*128;

        unsigned bw[2][2][4];
        uint32_t tsh[2][2][4][2];
        #pragma unroll
        for (int g = 0; g < 2; g++)
            #pragma unroll
            for (int s = 0; s < 2; s++) {
                *(uint4*)bw[g][s] = *(const uint4*)(brow[g][s] + (m0 >> 5));
                #pragma unroll
                for (int wi = 0; wi < 4; wi++) {
                    tsh[g][s][wi][0] = bw[g][s][wi] << (7 - c2);
                    tsh[g][s][wi][1] = bw[g][s][wi] << (6 - c2);
                }
            }

        #pragma unroll
        for (int half = 0; half < 2; half++) {
            uint32_t ah[2][4][4];
            #pragma unroll
            for (int kc = 0; kc < 4; kc++) {
                int mloc = half*64 + kc*16;
                int mA = mloc + c2, mB = mA + 8;
                uint2 pa = *(const uint2*)(pks + mA);
                uint2 pb = *(const uint2*)(pks + mB);
                uint32_t BpA = prmt(pa.x, pa.y, 0x5410u), BnA = prmt(pa.x, pa.y, 0x7632u);
                uint32_t BpB = prmt(pb.x, pb.y, 0x5410u), BnB = prmt(pb.x, pb.y, 0x7632u);
                int wi = 2*half + (kc >> 1);
                uint32_t selA = (kc & 1) ? 0xEEAAu : 0xCC88u;
                uint32_t selB = (kc & 1) ? 0xFFBBu : 0xDD99u;
                #pragma unroll
                for (int g = 0; g < 2; g++) {
                    #pragma unroll
                    for (int s = 0; s < 2; s++) {
                        uint32_t ta = tsh[g][s][wi][0];
                        uint32_t tb = tsh[g][s][wi][1];
                        uint32_t maskA = prmt(ta, tb, selA);
                        uint32_t maskB = prmt(ta, tb, selB);
                        uint32_t wA = max_bf2(mul_bf2(Ap2[g][s], BpA),
                                              mul_bf2(An2[g][s], BnA)) & maskA;
                        uint32_t wB = max_bf2(mul_bf2(Ap2[g][s], BpB),
                                              mul_bf2(An2[g][s], BnB)) & maskB;
                        ah[g][kc][s]     = wA;
                        ah[g][kc][s + 2] = wB;
                    }
                }
            }
            #pragma unroll
            for (int ko = 0; ko < 2; ko++) {
                #pragma unroll
                for (int g = 0; g < 2; g++) {
                    mma_bf16(accD[g], ah[g][2*ko],   ones2);
                    mma_bf16(accD[g], ah[g][2*ko+1], ones2);
                }
                #pragma unroll
                for (int dt = 0; dt < 8; dt++) {
                    uint32_t bh[4];
                    ldsm_x4(bh, sbuf + VH_OFF + bOff + dt*2176 + (half*2+ko)*64);
                    #pragma unroll
                    for (int g = 0; g < 2; g++) {
                        mma_bf16(acc[g][dt], ah[g][2*ko],   bh+0);
                        mma_bf16(acc[g][dt], ah[g][2*ko+1], bh+2);
                    }
                }
            }
        }
        __syncthreads();
    }

    if (partial) {
        if ((lane & 3) == 0) {
            #pragma unroll
            for (int g = 0; g < 2; g++) {
                pden[(size_t)seg*NN + rbase + g*16 + qr]     = accD[g][0];
                pden[(size_t)seg*NN + rbase + g*16 + 8 + qr] = accD[g][2];
            }
        }
        #pragma unroll
        for (int g = 0; g < 2; g++) {
            float* p0 = pnum + ((size_t)seg*NN + rbase + g*16 + qr)*64;
            float* p1 = pnum + ((size_t)seg*NN + rbase + g*16 + 8 + qr)*64;
            #pragma unroll
            for (int dt = 0; dt < 8; dt++) {
                *(float2*)(p0 + dt*8 + c2) = make_float2(acc[g][dt][0], acc[g][dt][1]);
                *(float2*)(p1 + dt*8 + c2) = make_float2(acc[g][dt][2], acc[g][dt][3]);
            }
        }
    } else {
        #pragma unroll
        for (int g = 0; g < 2; g++) {
            float inv0 = 1.0f / accD[g][0], inv1 = 1.0f / accD[g][2];
            int r0 = rbase + g*16 + qr, r1 = r0 + 8;
            #pragma unroll
            for (int dt = 0; dt < 8; dt++) {
                float z0 = acc[g][dt][0]*inv0, z1 = acc[g][dt][1]*inv0;
                float z2 = acc[g][dt][2]*inv1, z3 = acc[g][dt][3]*inv1;
                z0 = (z0 > 0.f) ? z0 : expm1f(z0);
                z1 = (z1 > 0.f) ? z1 : expm1f(z1);
                z2 = (z2 > 0.f) ? z2 : expm1f(z2);
                z3 = (z3 > 0.f) ? z3 : expm1f(z3);
                uint32_t h0, l0, h1, l1;
                packsplit(z0, z1, h0, l0);
                packsplit(z2, z3, h1, l1);
                size_t o0 = (size_t)r0*ldout + coloff + dt*8 + c2;
                size_t o1 = (size_t)r1*ldout + coloff + dt*8 + c2;
                *(uint32_t*)(out_hi + o0) = h0;
                *(uint32_t*)(out_lo + o0) = l0;
                *(uint32_t*)(out_hi + o1) = h1;
                *(uint32_t*)(out_lo + o1) = l1;
            }
        }
    }
}

// ------------- fused: combine K-split partials + ELU + log_softmax -> out -------------
__global__ void k_comb_final(const float* __restrict__ pnum, const float* __restrict__ pden,
                             float* __restrict__ out)
{
    int gw = (blockIdx.x*blockDim.x + threadIdx.x) >> 5;
    int lane = threadIdx.x & 31;
    if (gw >= NN) return;
    float den = 0.f;
    #pragma unroll
    for (int s = 0; s < SPLIT; s++) den += pden[(size_t)s*NN + gw];
    float a0 = 0.f, a1 = 0.f;
    #pragma unroll
    for (int s = 0; s < SPLIT; s++) {
        const float* p = pnum + ((size_t)s*NN + gw)*64;
        a0 += p[lane]; a1 += p[lane+32];
    }
    float inv = 1.0f / den;
    float z0 = a0*inv, z1 = a1*inv;
    z0 = (z0 > 0.f) ? z0 : expm1f(z0);
    z1 = (z1 > 0.f) ? z1 : expm1f(z1);
    float mx = fmaxf(z0, z1);
    #pragma unroll
    for (int o = 16; o; o >>= 1) mx = fmaxf(mx, __shfl_xor_sync(0xFFFFFFFFu, mx, o));
    float se = expf(z0 - mx) + expf(z1 - mx);
    #pragma unroll
    for (int o = 16; o; o >>= 1) se += __shfl_xor_sync(0xFFFFFFFFu, se, o);
    float lse = mx + logf(se);
    out[(size_t)gw*64 + lane]      = z0 - lse;
    out[(size_t)gw*64 + lane + 32] = z1 - lse;
}

extern "C" void kernel_launch(void* const* d_in, const int* in_sizes, int n_in,
                              void* d_out, int out_size)
{
    const float* x     = (const float*)d_in[0];
    const int*   adj   = (const int*)  d_in[1];
    const float* W     = (const float*)d_in[2];
    const float* asrc  = (const float*)d_in[3];
    const float* adst  = (const float*)d_in[4];
    const float* Wo    = (const float*)d_in[5];
    const float* aosrc = (const float*)d_in[6];
    const float* aodst = (const float*)d_in[7];
    float* out = (float*)d_out;

    void* sp = nullptr;  cudaGetSymbolAddress(&sp, g_scratch);
    void* bpv = nullptr; cudaGetSymbolAddress(&bpv, g_bits);
    void* bfv = nullptr; cudaGetSymbolAddress(&bfv, g_bf);
    float* S = (float*)sp;
    unsigned* bits = (unsigned*)bpv;
    __nv_bfloat16* BF = (__nv_bfloat16*)bfv;

    float* h2     = S;
    float* ApM    = h2  + (size_t)NN*DD;
    float* AnM    = ApM + (size_t)HH*NN;
    uint32_t* pkM = (uint32_t*)(AnM + (size_t)HH*NN);
    float* ApO    = (float*)(pkM + (size_t)HH*NN);
    float* AnO    = ApO + NN;
    uint32_t* pkO = (uint32_t*)(AnO + NN);
    float* pnum   = (float*)(pkO + NN);
    float* pden   = pnum + (size_t)SPLIT*NN*DD;
    float* gpart  = pnum;

    __nv_bfloat16* x_hi   = BF;
    __nv_bfloat16* x_lo   = x_hi   + (size_t)NN*FF;
    __nv_bfloat16* Wt_hi  = x_lo   + (size_t)NN*FF;
    __nv_bfloat16* Wt_lo  = Wt_hi  + (size_t)HH*FF*DD;
    __nv_bfloat16* WhT_hi = Wt_lo  + (size_t)HH*FF*DD;
    __nv_bfloat16* WhT_lo = WhT_hi + (size_t)NN*FF;
    __nv_bfloat16* hc_hi  = WhT_lo + (size_t)NN*FF;
    __nv_bfloat16* hc_lo  = hc_hi  + (size_t)NN*FF;
    __nv_bfloat16* Wot_hi = hc_lo  + (size_t)NN*FF;
    __nv_bfloat16* Wot_lo = Wot_hi + (size_t)FF*DD;
    __nv_bfloat16* WoT_hi = Wot_lo + (size_t)FF*DD;

    cudaFuncSetAttribute(k_gemm_f, cudaFuncAttributeMaxDynamicSharedMemorySize, SMEM_G);
    cudaFuncSetAttribute(k_gemm2_part, cudaFuncAttributeMaxDynamicSharedMemorySize, SMEM_G);
    cudaFuncSetAttribute(k_gemm2_fin, cudaFuncAttributeMaxDynamicSharedMemorySize, 64*132*4);
    cudaFuncSetAttribute(k_attn_mma, cudaFuncAttributeMaxDynamicSharedMemorySize, 3*17920);

    // 0) prep (x split + W/Wo transpose-split + adj->bits, co-scheduled)
    k_prep<<<dim3(2048, 1, 3), 256>>>(x, W, Wo, x_hi, x_lo, Wt_hi, Wt_lo, Wot_hi, Wot_lo,
                                      adj, bits);
    // 1) gemm1 fused
    k_gemm_f<<<dim3(NN/128, FF/64), 256, SMEM_G>>>(x_hi, x_lo, Wt_hi, Wt_lo, FF,
        asrc, adst, ApM, AnM, pkM, WhT_hi, WhT_lo);
    // 2) main attention (V hi-only, 128-thread CTAs, 3/SM)
    k_attn_mma<<<dim3(NN/128, HH, 1), 128, 3*17920>>>(WhT_hi,
        ApM, AnM, pkM, bits, hc_hi, hc_lo, FF, NN, nullptr, nullptr, 0);
    // 3) gemm2: 4-way K-split partials + finish
    k_gemm2_part<<<dim3(NN/128, 4), 256, SMEM_G>>>(hc_hi, hc_lo, Wot_hi, Wot_lo, gpart);
    k_gemm2_fin<<<NN/128, 256, 64*132*4>>>(gpart, aosrc, aodst, ApO, AnO, pkO, WoT_hi);
    // 4) out-head attention (V hi-only), 8-way m-split
    k_attn_mma<<<dim3(NN/128, 1, SPLIT), 128, 3*17920>>>(WoT_hi,
        ApO, AnO, pkO, bits, nullptr, nullptr, DD, NN/SPLIT, pnum, pden, 1);
    // 5) combine + ELU + log_softmax -> out (fused)
    k_comb_final<<<(NN*32 + 255)/256, 256>>>(pnum, pden, out);
}